// round 4
// baseline (speedup 1.0000x reference)
#include <cuda_runtime.h>
#include <cstdint>

#define TLEN   8192
#define BATCH  128
#define NS     128
#define EMITN  64
#define NT     512

// ---- packed f32x2 helpers (sm_103a) ----
__device__ __forceinline__ void fma2(unsigned long long& d, unsigned long long a, unsigned long long b) {
    asm("fma.rn.f32x2 %0, %1, %2, %0;" : "+l"(d) : "l"(a), "l"(b));
}
__device__ __forceinline__ unsigned long long mul2(unsigned long long a, unsigned long long b) {
    unsigned long long d;
    asm("mul.rn.f32x2 %0, %1, %2;" : "=l"(d) : "l"(a), "l"(b));
    return d;
}
__device__ __forceinline__ unsigned long long padd(unsigned long long a, unsigned long long b) {
    unsigned long long d;
    asm("add.rn.f32x2 %0, %1, %2;" : "=l"(d) : "l"(a), "l"(b));
    return d;
}
__device__ __forceinline__ unsigned long long pk(float lo, float hi) {
    unsigned long long r;
    asm("mov.b64 %0, {%1, %2};" : "=l"(r) : "f"(lo), "f"(hi));
    return r;
}
__device__ __forceinline__ float hsum2(unsigned long long v) {
    float lo, hi;
    asm("mov.b64 {%0, %1}, %2;" : "=f"(lo), "=f"(hi) : "l"(v));
    return lo + hi;
}

__global__ __launch_bounds__(NT, 1)
void hmm_forward_kernel(const float* __restrict__ inputs,
                        const float* __restrict__ Ivec,
                        const float* __restrict__ Amat,
                        const float* __restrict__ Bmat,
                        float* __restrict__ out)
{
    __shared__ float Bsh[EMITN * NS];                     // 32 KB
    __shared__ unsigned char obs_sm[TLEN];                // 8 KB
    __shared__ __align__(16) float ubuf[2][NS];           // double-buffered v_t
    __shared__ __align__(16) unsigned long long rpsm[3][NS]; // partial dots, quarters 1..3
    __shared__ __align__(16) float zs1[2][8];             // relay stage-1 partials
    __shared__ float sc_sm[2];                            // ready-made pow2 scale
    __shared__ __align__(16) float znext[4];
    __shared__ int stot_sm;

    const int tid  = threadIdx.x;
    const int s    = tid & 127;     // output state
    const int q    = tid >> 7;      // k-quarter: k in [32q, 32q+32)
    const int w    = tid >> 5;
    const int lane = tid & 31;
    const int b    = blockIdx.x;

    // ---- prologue: B into smem ----
    for (int i = tid; i < EMITN * NS; i += NT) Bsh[i] = Bmat[i];

    // ---- prologue: one-hot -> obs index (exact dot with iota) ----
    {
        const float* xin = inputs + (size_t)b * TLEN * EMITN;
        for (int t = tid; t < TLEN; t += NT) {
            const float4* r = (const float4*)(xin + (size_t)t * EMITN);
            float idx = 0.0f;
            #pragma unroll
            for (int j = 0; j < 16; j++) {
                float4 v = r[j];
                idx = fmaf((float)(4 * j + 0), v.x, idx);
                idx = fmaf((float)(4 * j + 1), v.y, idx);
                idx = fmaf((float)(4 * j + 2), v.z, idx);
                idx = fmaf((float)(4 * j + 3), v.w, idx);
            }
            obs_sm[t] = (unsigned char)__float2int_rn(idx);
        }
    }

    // ---- prologue: A[k][s] for k in [32q, 32q+32) -> 16 packed u64 ----
    unsigned long long Ar[16];
    {
        const int k0 = 32 * q;
        #pragma unroll
        for (int j = 0; j < 16; j++) {
            float a0 = Amat[(k0 + 2 * j) * NS + s];
            float a1 = Amat[(k0 + 2 * j + 1) * NS + s];
            Ar[j] = pk(a0, a1);
        }
    }
    float Ival = Ivec[s];
    __syncthreads();

    // ---- t = 0: v0 = E0 * I ----
    {
        int o0 = obs_sm[0];
        float v0 = Bsh[o0 * NS + s] * Ival;
        if (q == 0) ubuf[0][s] = v0;
    }
    __syncthreads();

    // ---- prime the scaling relay ----
    if (w == 0) {
        float vs = (ubuf[0][lane] + ubuf[0][lane + 32]) + (ubuf[0][lane + 64] + ubuf[0][lane + 96]);
        #pragma unroll
        for (int off = 16; off > 0; off >>= 1) vs += __shfl_xor_sync(0xffffffffu, vs, off);
        if (lane == 0) { zs1[0][0] = vs; sc_sm[0] = 1.0f; }
        else if (lane < 8) zs1[0][lane] = 0.0f;
    }
    __syncthreads();

    int   Stot  = 0;                  // accumulated shifts (valid only on tid==256)
    float Elast = 0.f, Rlast = 0.f;

    // ---- main recurrence ----
    for (int t = 1; t < TLEN; t++) {
        const int pb = (t - 1) & 1, cb = t & 1;

        // ===== FMA phase =====
        float E = 0.f, Escf = 0.f;
        if (q == 0) {                          // prefetch: obs -> B, and the pow2 scale
            int o = obs_sm[t];
            float scf = sc_sm[pb];
            E = Bsh[o * NS + s];
            Escf = E * scf;
        }

        const ulonglong2* up = (const ulonglong2*)ubuf[pb] + 8 * q;
        ulonglong2 c0 = up[0], c1 = up[1], c2 = up[2], c3 = up[3];
        unsigned long long acc0 = mul2(c0.x, Ar[0]);
        unsigned long long acc1 = mul2(c0.y, Ar[1]);
        unsigned long long acc2 = mul2(c1.x, Ar[2]);
        unsigned long long acc3 = mul2(c1.y, Ar[3]);
        fma2(acc0, c2.x, Ar[4]);  fma2(acc1, c2.y, Ar[5]);
        fma2(acc2, c3.x, Ar[6]);  fma2(acc3, c3.y, Ar[7]);
        ulonglong2 c4 = up[4], c5 = up[5], c6 = up[6], c7 = up[7];
        fma2(acc0, c4.x, Ar[8]);   fma2(acc1, c4.y, Ar[9]);
        fma2(acc2, c5.x, Ar[10]);  fma2(acc3, c5.y, Ar[11]);
        fma2(acc0, c6.x, Ar[12]);  fma2(acc1, c6.y, Ar[13]);
        fma2(acc2, c7.x, Ar[14]);  fma2(acc3, c7.y, Ar[15]);

        unsigned long long pp = padd(padd(acc0, acc1), padd(acc2, acc3));
        if (q != 0) rpsm[q - 1][s] = pp;       // STS.64

        __syncthreads();                        // BAR1: partials ready

        // ===== combine phase (short, role-split) =====
        if (q == 0) {
            float2 r1 = *(const float2*)&rpsm[0][s];
            float2 r2 = *(const float2*)&rpsm[1][s];
            float2 r3 = *(const float2*)&rpsm[2][s];
            float R = (hsum2(pp) + (r1.x + r1.y)) + ((r2.x + r2.y) + (r3.x + r3.y));
            ubuf[cb][s] = Escf * R;
            Elast = E; Rlast = R;
        } else if (tid >= 128 && tid < 136) {
            // relay stage 1: 8 lanes sum 16 floats each of v_{t-1}
            int l = tid - 128;
            const float4* vp = (const float4*)ubuf[pb] + 4 * l;
            float4 a = vp[0], bb = vp[1], c = vp[2], d = vp[3];
            float t0 = ((a.x + a.y) + (a.z + a.w)) + ((bb.x + bb.y) + (bb.z + bb.w));
            float t1 = ((c.x + c.y) + (c.z + c.w)) + ((d.x + d.y) + (d.z + d.w));
            zs1[cb][l] = t0 + t1;
        } else if (tid == 256) {
            // relay stage 2: Z (3-step stale) -> damped pow2 scale + Stot
            float4 za = *(const float4*)&zs1[pb][0];
            float4 zb = *(const float4*)&zs1[pb][4];
            float Z = ((za.x + za.y) + (za.z + za.w)) + ((zb.x + zb.y) + (zb.z + zb.w));
            int e = ((((__float_as_int(Z) >> 23) & 255) - 127) >> 2);   // gain 1/4, delay 3
            if (t < TLEN - 1) Stot += e;
            sc_sm[cb] = __int_as_float((127 - e) << 23);                 // 2^{-e}, exact
        }
        __syncthreads();                        // BAR2: ubuf(t) + relay ready
    }

    // ---- epilogue ----
    if (tid == 256) stot_sm = Stot;
    if (q == 0) {
        float rr = Rlast;
        #pragma unroll
        for (int off = 16; off > 0; off >>= 1) rr += __shfl_xor_sync(0xffffffffu, rr, off);
        if (lane == 0) znext[w] = rr;
    }
    __syncthreads();

    if (q == 0) {
        float4 zn = *(const float4*)znext;
        float ZT1 = (zn.x + zn.y) + (zn.z + zn.w);     // = sum(v_{T-1})  (A rows sum to 1)
        out[b * NS + s] = Elast * Rlast / ZT1;         // alpha_f (pow2 factors cancel)
    }

    if (w == 0) {
        const float* ul = ubuf[(TLEN - 1) & 1];
        float vT = (ul[lane] + ul[lane + 32]) + (ul[lane + 64] + ul[lane + 96]);
        #pragma unroll
        for (int off = 16; off > 0; off >>= 1) vT += __shfl_xor_sync(0xffffffffu, vT, off);
        if (lane == 0) {
            double ll = log((double)vT) + (double)stot_sm * 0.6931471805599453;
            out[BATCH * NS + b] = (float)ll;           // loglik
        }
    }
}

extern "C" void kernel_launch(void* const* d_in, const int* in_sizes, int n_in,
                              void* d_out, int out_size)
{
    const float* inputs = (const float*)d_in[0];   // [128, 8192, 64]
    const float* Ivec   = (const float*)d_in[1];   // [128]
    const float* Amat   = (const float*)d_in[2];   // [128, 128]
    const float* Bmat   = (const float*)d_in[3];   // [64, 128]
    float* out = (float*)d_out;                    // alpha_f [128,128] ++ loglik [128]

    hmm_forward_kernel<<<BATCH, NT>>>(inputs, Ivec, Amat, Bmat, out);
}

// round 5
// speedup vs baseline: 1.4446x; 1.4446x over previous
#include <cuda_runtime.h>
#include <cstdint>

#define TLEN   8192
#define BATCH  128
#define NS     128
#define EMITN  64
#define NT     160   // 4 compute warps (128 state threads) + 1 relay warp

// ---- packed f32x2 helpers (sm_103a) ----
__device__ __forceinline__ void fma2(unsigned long long& d, unsigned long long a, unsigned long long b) {
    asm("fma.rn.f32x2 %0, %1, %2, %0;" : "+l"(d) : "l"(a), "l"(b));
}
__device__ __forceinline__ unsigned long long mul2(unsigned long long a, unsigned long long b) {
    unsigned long long d;
    asm("mul.rn.f32x2 %0, %1, %2;" : "=l"(d) : "l"(a), "l"(b));
    return d;
}
__device__ __forceinline__ unsigned long long padd(unsigned long long a, unsigned long long b) {
    unsigned long long d;
    asm("add.rn.f32x2 %0, %1, %2;" : "=l"(d) : "l"(a), "l"(b));
    return d;
}
__device__ __forceinline__ unsigned long long pk(float lo, float hi) {
    unsigned long long r;
    asm("mov.b64 %0, {%1, %2};" : "=l"(r) : "f"(lo), "f"(hi));
    return r;
}
__device__ __forceinline__ float hsum2(unsigned long long v) {
    float lo, hi;
    asm("mov.b64 {%0, %1}, %2;" : "=f"(lo), "=f"(hi) : "l"(v));
    return lo + hi;
}

__global__ __launch_bounds__(NT, 1)
void hmm_forward_kernel(const float* __restrict__ inputs,
                        const float* __restrict__ Ivec,
                        const float* __restrict__ Amat,
                        const float* __restrict__ Bmat,
                        float* __restrict__ out)
{
    __shared__ float Bsh[EMITN * NS];              // 32 KB
    __shared__ unsigned char obs_sm[TLEN];         // 8 KB
    __shared__ __align__(16) float ubuf[2][NS];    // double-buffered v_t
    __shared__ __align__(16) float zs1[2][8];      // relay stage-1 partials
    __shared__ float sc_sm[2];                     // exact pow2 scale (relay output)
    __shared__ __align__(16) float znext[4];       // epilogue: sum R
    __shared__ __align__(16) float zvs[4];         // epilogue: sum v_T
    __shared__ int stot_sm;

    const int tid  = threadIdx.x;
    const int s    = tid & 127;     // state index (compute threads)
    const int w    = tid >> 5;
    const int lane = tid & 31;
    const int b    = blockIdx.x;
    const bool isCompute = (tid < 128);

    // ---- prologue: B into smem ----
    for (int i = tid; i < EMITN * NS; i += NT) Bsh[i] = Bmat[i];

    // ---- prologue: one-hot -> obs index (exact dot with iota) ----
    {
        const float* xin = inputs + (size_t)b * TLEN * EMITN;
        for (int t = tid; t < TLEN; t += NT) {
            const float4* r = (const float4*)(xin + (size_t)t * EMITN);
            float idx = 0.0f;
            #pragma unroll
            for (int j = 0; j < 16; j++) {
                float4 v = r[j];
                idx = fmaf((float)(4 * j + 0), v.x, idx);
                idx = fmaf((float)(4 * j + 1), v.y, idx);
                idx = fmaf((float)(4 * j + 2), v.z, idx);
                idx = fmaf((float)(4 * j + 3), v.w, idx);
            }
            obs_sm[t] = (unsigned char)__float2int_rn(idx);
        }
    }

    // ---- prologue: full A column s into registers (64 packed f32x2) ----
    unsigned long long Ar[64];
    if (isCompute) {
        #pragma unroll
        for (int j = 0; j < 64; j++) {
            float a0 = Amat[(2 * j) * NS + s];
            float a1 = Amat[(2 * j + 1) * NS + s];
            Ar[j] = pk(a0, a1);
        }
    }

    // ---- init: v0 = E0*I, relay buffers ----
    if (isCompute) {
        float Ival = Ivec[s];
        __syncthreads();           // Bsh + obs ready
        int o0 = obs_sm[0];
        ubuf[0][s] = Bsh[o0 * NS + s] * Ival;
    } else {
        __syncthreads();
        if (lane < 8) { zs1[0][lane] = 0.125f; zs1[1][lane] = 0.125f; }  // Z=1 -> e=0
        if (lane == 0) { sc_sm[0] = 1.0f; sc_sm[1] = 1.0f; }
    }
    __syncthreads();

    int   Stot  = 0;                  // (valid on tid==128)
    float Elast = 0.f, Rlast = 0.f, vlast = 0.f;

    // ---- main recurrence: ONE barrier per step ----
    for (int t = 1; t < TLEN; t++) {
        const int pb = (t - 1) & 1, cb = t & 1;

        if (isCompute) {
            // prefetch scale + emission (independent of FMA chain)
            float scf = sc_sm[pb];
            int o = obs_sm[t];
            float E = Bsh[o * NS + s];
            float Escf = E * scf;

            // full dot: R[s] = sum_k v_{t-1}[k] * A[k][s]
            const ulonglong2* up = (const ulonglong2*)ubuf[pb];   // 32 x 16B, broadcast
            unsigned long long acc[8];
            #pragma unroll
            for (int j = 0; j < 4; j++) {
                ulonglong2 c = up[j];
                acc[2 * j]     = mul2(c.x, Ar[2 * j]);
                acc[2 * j + 1] = mul2(c.y, Ar[2 * j + 1]);
            }
            #pragma unroll
            for (int j = 4; j < 32; j++) {
                ulonglong2 c = up[j];
                fma2(acc[(2 * j) & 7],     c.x, Ar[2 * j]);
                fma2(acc[(2 * j + 1) & 7], c.y, Ar[2 * j + 1]);
            }
            unsigned long long p0 = padd(padd(acc[0], acc[1]), padd(acc[2], acc[3]));
            unsigned long long p1 = padd(padd(acc[4], acc[5]), padd(acc[6], acc[7]));
            float R = hsum2(padd(p0, p1));

            float v = Escf * R;
            ubuf[cb][s] = v;
            Elast = E; Rlast = R; vlast = v;
        } else {
            // ---- relay warp: pipelined stale-Z pow2 controller (delay-3, gain 1/4) ----
            float4 za, zb;
            if (lane == 0) {   // stage B inputs: last step's partials
                za = *(const float4*)&zs1[pb][0];
                zb = *(const float4*)&zs1[pb][4];
            }
            // stage A: 16-float partial sums of v_{t-1}
            float4 a = ((const float4*)ubuf[pb])[lane];
            float zsum = (a.x + a.y) + (a.z + a.w);
            zsum += __shfl_xor_sync(0xffffffffu, zsum, 1);
            zsum += __shfl_xor_sync(0xffffffffu, zsum, 2);
            if ((lane & 3) == 0) zs1[cb][lane >> 2] = zsum;
            if (lane == 0) {
                float Z = ((za.x + za.y) + (za.z + za.w)) + ((zb.x + zb.y) + (zb.z + zb.w));
                int e = ((((__float_as_int(Z) >> 23) & 255) - 127) >> 2);  // damped
                if (t < TLEN - 1) Stot += e;            // scf written here is applied at t+1
                sc_sm[cb] = __int_as_float((127 - e) << 23);   // 2^{-e}, exact
            }
        }
        __syncthreads();   // v_t, zs1, scf all published
    }

    // ---- epilogue ----
    if (isCompute) {
        float rr = Rlast, vv = vlast;
        #pragma unroll
        for (int off = 16; off > 0; off >>= 1) {
            rr += __shfl_xor_sync(0xffffffffu, rr, off);
            vv += __shfl_xor_sync(0xffffffffu, vv, off);
        }
        if (lane == 0) { znext[w] = rr; zvs[w] = vv; }
    } else if (tid == 128) {
        stot_sm = Stot;
    }
    __syncthreads();

    if (isCompute) {
        float4 zn = *(const float4*)znext;
        float SR = (zn.x + zn.y) + (zn.z + zn.w);      // = sum(v_{T-2}) (A rows sum to 1)
        out[b * NS + s] = Elast * Rlast / SR;          // alpha_f (pow2 factors cancel)
    }
    if (tid == 0) {
        float4 zv = *(const float4*)zvs;
        float SV = (zv.x + zv.y) + (zv.z + zv.w);      // sum(v_{T-1})
        double ll = log((double)SV) + (double)stot_sm * 0.6931471805599453;
        out[BATCH * NS + b] = (float)ll;               // loglik
    }
}

extern "C" void kernel_launch(void* const* d_in, const int* in_sizes, int n_in,
                              void* d_out, int out_size)
{
    const float* inputs = (const float*)d_in[0];   // [128, 8192, 64]
    const float* Ivec   = (const float*)d_in[1];   // [128]
    const float* Amat   = (const float*)d_in[2];   // [128, 128]
    const float* Bmat   = (const float*)d_in[3];   // [64, 128]
    float* out = (float*)d_out;                    // alpha_f [128,128] ++ loglik [128]

    hmm_forward_kernel<<<BATCH, NT>>>(inputs, Ivec, Amat, Bmat, out);
}